// round 1
// baseline (speedup 1.0000x reference)
#include <cuda_runtime.h>

#define N_NODES 50000
#define N_EDGES 1600000
#define N_GRAPHS 256
#define HID 128

// ---------------- scratch (static device globals; no runtime alloc) --------
__device__ float g_bufA[(size_t)N_NODES * HID];
__device__ float g_bufB[(size_t)N_NODES * HID];
__device__ float g_bufC[(size_t)N_NODES * HID];
__device__ int   g_src[N_EDGES];
__device__ int   g_dst[N_EDGES];
__device__ int   g_batch[N_NODES];
__device__ float g_coef[N_EDGES];
__device__ float g_deg[N_NODES];
__device__ float g_dinv[N_NODES];
__device__ float g_self[N_NODES];
__device__ float g_emb[N_GRAPHS * HID];
__device__ float g_cnt[N_GRAPHS];
__device__ int   g_is64;

// ---------------- dtype detection: int64 vs int32 indices ------------------
// Values are random in [0, 50000). If the buffer is int64 (little-endian),
// every odd 32-bit word is 0. If int32, odd words are random nonzero values.
__global__ void k_detect(const unsigned* ei) {
    if (threadIdx.x == 0 && blockIdx.x == 0) {
        int is64 = 1;
#pragma unroll
        for (int i = 1; i < 16; i += 2)
            if (ei[i] != 0u) is64 = 0;
        g_is64 = is64;
    }
}

// Convert edge_index (2 x E) and batch to int32 scratch; init deg to 1 (self loop).
__global__ void k_convert(const void* ei, const void* batch) {
    int t = blockIdx.x * blockDim.x + threadIdx.x;
    int is64 = g_is64;
    if (t < N_EDGES) {
        if (is64) {
            const long long* p = (const long long*)ei;
            g_src[t] = (int)p[t];
            g_dst[t] = (int)p[N_EDGES + t];
        } else {
            const int* p = (const int*)ei;
            g_src[t] = p[t];
            g_dst[t] = p[N_EDGES + t];
        }
    }
    if (t < N_NODES) {
        g_batch[t] = is64 ? (int)((const long long*)batch)[t]
                          : ((const int*)batch)[t];
        g_deg[t] = 1.0f;  // self-loop weight
    }
}

__global__ void k_deg(const float* __restrict__ ew) {
    int t = blockIdx.x * blockDim.x + threadIdx.x;
    if (t < N_EDGES) atomicAdd(&g_deg[g_dst[t]], ew[t]);
}

__global__ void k_dinv() {
    int t = blockIdx.x * blockDim.x + threadIdx.x;
    if (t < N_NODES) {
        float d = g_deg[t];
        float r = (d > 0.0f) ? rsqrtf(d) : 0.0f;
        g_dinv[t] = r;
        g_self[t] = r * r;
    }
}

__global__ void k_coef(const float* __restrict__ ew) {
    int t = blockIdx.x * blockDim.x + threadIdx.x;
    if (t < N_EDGES)
        g_coef[t] = g_dinv[g_src[t]] * g_dinv[g_dst[t]] * ew[t];
}

// ---------------- GEMM: C[M,128] = (relu? max(A,0):A) @ W[128,128] ---------
// BM=64, BN=128, full K=128 in 4 k-tiles of 32. 256 threads, 4x8 micro-tile.
__global__ void __launch_bounds__(256) k_gemm(const float* __restrict__ A,
                                              const float* __restrict__ W,
                                              float* __restrict__ C,
                                              int M, int relu) {
    __shared__ float As[32][68];    // [k][m], padded row (68*4B, 16B aligned)
    __shared__ float Ws[32][128];   // [k][n]
    const int tid = threadIdx.x;
    const int tx = tid & 15, ty = tid >> 4;
    const int m0 = blockIdx.x * 64;

    float acc[4][8];
#pragma unroll
    for (int i = 0; i < 4; i++)
#pragma unroll
        for (int j = 0; j < 8; j++) acc[i][j] = 0.0f;

    for (int k0 = 0; k0 < 128; k0 += 32) {
        // A tile: 64 rows x 32 cols = 512 float4; 2 per thread.
        // mapping r = idx&63 keeps smem stores conflict-free.
#pragma unroll
        for (int i = 0; i < 2; i++) {
            int idx = tid + i * 256;
            int r = idx & 63;
            int c4 = idx >> 6;   // 0..7
            int gm = m0 + r;
            float4 v = make_float4(0.f, 0.f, 0.f, 0.f);
            if (gm < M) v = *(const float4*)&A[(size_t)gm * 128 + k0 + c4 * 4];
            if (relu) {
                v.x = fmaxf(v.x, 0.f); v.y = fmaxf(v.y, 0.f);
                v.z = fmaxf(v.z, 0.f); v.w = fmaxf(v.w, 0.f);
            }
            As[c4 * 4 + 0][r] = v.x;
            As[c4 * 4 + 1][r] = v.y;
            As[c4 * 4 + 2][r] = v.z;
            As[c4 * 4 + 3][r] = v.w;
        }
        // W tile: 32 x 128 = 1024 float4; 4 per thread, coalesced.
#pragma unroll
        for (int i = 0; i < 4; i++) {
            int idx = tid + i * 256;
            int r = idx >> 5;
            int c4 = idx & 31;
            *(float4*)&Ws[r][c4 * 4] =
                *(const float4*)&W[(size_t)(k0 + r) * 128 + c4 * 4];
        }
        __syncthreads();
#pragma unroll
        for (int k = 0; k < 32; k++) {
            float4 a  = *(float4*)&As[k][ty * 4];
            float4 b0 = *(float4*)&Ws[k][tx * 4];
            float4 b1 = *(float4*)&Ws[k][64 + tx * 4];
            float av[4] = {a.x, a.y, a.z, a.w};
            float bv[8] = {b0.x, b0.y, b0.z, b0.w, b1.x, b1.y, b1.z, b1.w};
#pragma unroll
            for (int i = 0; i < 4; i++)
#pragma unroll
                for (int j = 0; j < 8; j++) acc[i][j] += av[i] * bv[j];
        }
        __syncthreads();
    }
#pragma unroll
    for (int i = 0; i < 4; i++) {
        int gm = m0 + ty * 4 + i;
        if (gm < M) {
            float4 o0 = make_float4(acc[i][0], acc[i][1], acc[i][2], acc[i][3]);
            float4 o1 = make_float4(acc[i][4], acc[i][5], acc[i][6], acc[i][7]);
            *(float4*)&C[(size_t)gm * 128 + tx * 4] = o0;
            *(float4*)&C[(size_t)gm * 128 + 64 + tx * 4] = o1;
        }
    }
}

// ---------------- out = bias + self_coef * hW  (self-loop term) ------------
__global__ void k_init_out(const float* __restrict__ hw,
                           const float* __restrict__ bias,
                           float* __restrict__ out) {
    int t = blockIdx.x * blockDim.x + threadIdx.x;
    if (t >= N_NODES * 32) return;
    int node = t >> 5, q = t & 31;
    float4 b = *(const float4*)&bias[q * 4];
    float s = g_self[node];
    float4 v = *(const float4*)&hw[(size_t)node * 128 + q * 4];
    float4 o = make_float4(b.x + s * v.x, b.y + s * v.y,
                           b.z + s * v.z, b.w + s * v.w);
    *(float4*)&out[(size_t)node * 128 + q * 4] = o;
}

// ---------------- edge scatter: out[dst] += coef * hW[src] -----------------
// One warp handles 32 edges: coalesced edge loads, then per-edge all 32 lanes
// gather one float4 of the 512B row and issue a vectorized red (no return).
__global__ void k_scatter(const float* __restrict__ hw, float* __restrict__ out) {
    int gt = blockIdx.x * blockDim.x + threadIdx.x;
    int lane = threadIdx.x & 31;
    int wid = gt >> 5;
    int e0 = wid * 32;
    if (e0 >= N_EDGES) return;
    int s = g_src[e0 + lane];
    int d = g_dst[e0 + lane];
    float c = g_coef[e0 + lane];
#pragma unroll 4
    for (int i = 0; i < 32; i++) {
        int si = __shfl_sync(0xffffffffu, s, i);
        int di = __shfl_sync(0xffffffffu, d, i);
        float ci = __shfl_sync(0xffffffffu, c, i);
        float4 v = *(const float4*)&hw[(size_t)si * 128 + lane * 4];
        float* p = &out[(size_t)di * 128 + lane * 4];
        asm volatile("red.global.add.v4.f32 [%0], {%1, %2, %3, %4};"
                     :: "l"(p), "f"(ci * v.x), "f"(ci * v.y),
                        "f"(ci * v.z), "f"(ci * v.w)
                     : "memory");
    }
}

// ---------------- mean pool ------------------------------------------------
__global__ void k_pool_zero() {
    int t = blockIdx.x * blockDim.x + threadIdx.x;
    if (t < N_GRAPHS * HID) g_emb[t] = 0.0f;
    if (t < N_GRAPHS) g_cnt[t] = 0.0f;
}

__global__ void k_pool(const float* __restrict__ h) {
    int gt = blockIdx.x * blockDim.x + threadIdx.x;
    int lane = threadIdx.x & 31;
    int node = gt >> 5;
    if (node >= N_NODES) return;
    int g = g_batch[node];
    float4 v = *(const float4*)&h[(size_t)node * 128 + lane * 4];
    float* p = &g_emb[g * 128 + lane * 4];
    asm volatile("red.global.add.v4.f32 [%0], {%1, %2, %3, %4};"
                 :: "l"(p), "f"(v.x), "f"(v.y), "f"(v.z), "f"(v.w)
                 : "memory");
    if (lane == 0) atomicAdd(&g_cnt[g], 1.0f);
}

// ---------------- classifier: out = (emb/cnt @ lw1 + lb1) @ lw2 + lb2 ------
__global__ void k_classify(const float* __restrict__ lw1,
                           const float* __restrict__ lb1,
                           const float* __restrict__ lw2,
                           const float* __restrict__ lb2,
                           float* __restrict__ out) {
    int lane = threadIdx.x & 31;
    int g = (blockIdx.x * blockDim.x + threadIdx.x) >> 5;
    if (g >= N_GRAPHS) return;
    float inv = 1.0f / fmaxf(g_cnt[g], 1.0f);
    float e[4];
#pragma unroll
    for (int j = 0; j < 4; j++) e[j] = g_emb[g * 128 + lane + 32 * j] * inv;
    float t[4] = {lb1[lane], lb1[lane + 32], lb1[lane + 64], lb1[lane + 96]};
#pragma unroll
    for (int k0 = 0; k0 < 4; k0++) {
#pragma unroll
        for (int kk = 0; kk < 32; kk++) {
            float a = __shfl_sync(0xffffffffu, e[k0], kk);
            int k = k0 * 32 + kk;
            t[0] += a * lw1[k * 128 + lane];
            t[1] += a * lw1[k * 128 + lane + 32];
            t[2] += a * lw1[k * 128 + lane + 64];
            t[3] += a * lw1[k * 128 + lane + 96];
        }
    }
#pragma unroll
    for (int o = 0; o < 10; o++) {
        float p = t[0] * lw2[lane * 10 + o] + t[1] * lw2[(lane + 32) * 10 + o] +
                  t[2] * lw2[(lane + 64) * 10 + o] + t[3] * lw2[(lane + 96) * 10 + o];
#pragma unroll
        for (int off = 16; off; off >>= 1)
            p += __shfl_down_sync(0xffffffffu, p, off);
        if (lane == 0) out[g * 10 + o] = p + lb2[o];
    }
}

// ---------------- launch ----------------------------------------------------
extern "C" void kernel_launch(void* const* d_in, const int* in_sizes, int n_in,
                              void* d_out, int out_size) {
    const float* x   = (const float*)d_in[0];
    const void*  ei  = d_in[1];
    const float* ew  = (const float*)d_in[2];
    const void*  bt  = d_in[3];
    const float* W1  = (const float*)d_in[4];
    const float* b1  = (const float*)d_in[5];
    const float* W2  = (const float*)d_in[6];
    const float* b2  = (const float*)d_in[7];
    const float* W3  = (const float*)d_in[8];
    const float* b3  = (const float*)d_in[9];
    const float* lw1 = (const float*)d_in[10];
    const float* lb1 = (const float*)d_in[11];
    const float* lw2 = (const float*)d_in[12];
    const float* lb2 = (const float*)d_in[13];
    float* out = (float*)d_out;

    float *bufA, *bufB, *bufC;
    cudaGetSymbolAddress((void**)&bufA, g_bufA);
    cudaGetSymbolAddress((void**)&bufB, g_bufB);
    cudaGetSymbolAddress((void**)&bufC, g_bufC);

    const int EB  = (N_EDGES + 255) / 256;            // 6250
    const int NB  = (N_NODES + 255) / 256;            // 196
    const int NB32 = (N_NODES * 32 + 255) / 256;      // 6250
    const int SB  = (N_EDGES / 32 + 7) / 8;           // 6250 (warp per 32 edges)
    const int PB  = (N_NODES + 7) / 8;                // 6250 (warp per node)
    const int GB  = (N_NODES + 63) / 64;              // 782

    k_detect<<<1, 32>>>((const unsigned*)ei);
    k_convert<<<EB, 256>>>(ei, bt);
    k_deg<<<EB, 256>>>(ew);
    k_dinv<<<NB, 256>>>();
    k_coef<<<EB, 256>>>(ew);

    // layer 1: x -> bufB
    k_gemm<<<GB, 256>>>(x, W1, bufA, N_NODES, 0);
    k_init_out<<<NB32, 256>>>(bufA, b1, bufB);
    k_scatter<<<SB, 256>>>(bufA, bufB);
    // layer 2: relu(bufB) -> bufC
    k_gemm<<<GB, 256>>>(bufB, W2, bufA, N_NODES, 1);
    k_init_out<<<NB32, 256>>>(bufA, b2, bufC);
    k_scatter<<<SB, 256>>>(bufA, bufC);
    // layer 3: relu(bufC) -> bufB
    k_gemm<<<GB, 256>>>(bufC, W3, bufA, N_NODES, 1);
    k_init_out<<<NB32, 256>>>(bufA, b3, bufB);
    k_scatter<<<SB, 256>>>(bufA, bufB);

    k_pool_zero<<<(N_GRAPHS * HID + 255) / 256, 256>>>();
    k_pool<<<PB, 256>>>(bufB);
    k_classify<<<(N_GRAPHS * 32 + 255) / 256, 256>>>(lw1, lb1, lw2, lb2, out);
}

// round 2
// speedup vs baseline: 1.3597x; 1.3597x over previous
#include <cuda_runtime.h>

#define N_NODES 50000
#define N_EDGES 1600000
#define N_GRAPHS 256
#define HID 128

// ---------------- scratch (static device globals; no runtime alloc) --------
__device__ float g_bufA[(size_t)N_NODES * HID];
__device__ float g_bufB[(size_t)N_NODES * HID];
__device__ float g_bufC[(size_t)N_NODES * HID];
__device__ int   g_src[N_EDGES];
__device__ int   g_dst[N_EDGES];
__device__ int   g_csr_src[N_EDGES];
__device__ float g_csr_coef[N_EDGES];
__device__ int   g_cnt[N_NODES];
__device__ int   g_rowptr[N_NODES + 1];
__device__ int   g_cursor[N_NODES];
__device__ int   g_batch[N_NODES];
__device__ float g_deg[N_NODES];
__device__ float g_dinv[N_NODES];
__device__ float g_self[N_NODES];
__device__ float g_emb[N_GRAPHS * HID];
__device__ float g_gcnt[N_GRAPHS];
__device__ int   g_is64;

// ---------------- dtype detection: int64 vs int32 indices ------------------
// Values are random in [0, 50000). If buffer is int64 (LE), odd words are 0.
__global__ void k_detect(const unsigned* ei) {
    if (threadIdx.x == 0 && blockIdx.x == 0) {
        int is64 = 1;
#pragma unroll
        for (int i = 1; i < 16; i += 2)
            if (ei[i] != 0u) is64 = 0;
        g_is64 = is64;
    }
}

// init per-node state (deg=1 self-loop, cnt=0) and zero pool accumulators
__global__ void k_init_nodes() {
    int t = blockIdx.x * blockDim.x + threadIdx.x;
    if (t < N_NODES) { g_deg[t] = 1.0f; g_cnt[t] = 0; }
    if (t < N_GRAPHS * HID) g_emb[t] = 0.0f;
    if (t < N_GRAPHS) g_gcnt[t] = 0.0f;
}

// convert indices to int32 + weighted-degree & count histogram in one pass
__global__ void k_convert_hist(const void* ei, const void* batch,
                               const float* __restrict__ ew) {
    int t = blockIdx.x * blockDim.x + threadIdx.x;
    int is64 = g_is64;
    if (t < N_EDGES) {
        int s, d;
        if (is64) {
            const long long* p = (const long long*)ei;
            s = (int)p[t]; d = (int)p[N_EDGES + t];
        } else {
            const int* p = (const int*)ei;
            s = p[t]; d = p[N_EDGES + t];
        }
        g_src[t] = s;
        g_dst[t] = d;
        atomicAdd(&g_deg[d], ew[t]);
        atomicAdd(&g_cnt[d], 1);
    }
    if (t < N_NODES) {
        g_batch[t] = is64 ? (int)((const long long*)batch)[t]
                          : ((const int*)batch)[t];
    }
}

// single-block exclusive scan of g_cnt -> g_rowptr / g_cursor
__global__ void __launch_bounds__(1024) k_scan() {
    __shared__ int sh[1024];
    const int T = 1024;
    const int CH = (N_NODES + T - 1) / T;  // 49
    int tid = threadIdx.x;
    int lo = tid * CH;
    int hi = min(lo + CH, N_NODES);
    int s = 0;
    for (int i = lo; i < hi; i++) s += g_cnt[i];
    sh[tid] = s;
    __syncthreads();
    for (int off = 1; off < T; off <<= 1) {
        int v = sh[tid];
        int u = (tid >= off) ? sh[tid - off] : 0;
        __syncthreads();
        sh[tid] = v + u;
        __syncthreads();
    }
    int run = (tid > 0) ? sh[tid - 1] : 0;
    for (int i = lo; i < hi; i++) {
        g_rowptr[i] = run;
        g_cursor[i] = run;
        run += g_cnt[i];
    }
    if (tid == T - 1) g_rowptr[N_NODES] = run;
}

__global__ void k_dinv() {
    int t = blockIdx.x * blockDim.x + threadIdx.x;
    if (t < N_NODES) {
        float d = g_deg[t];
        float r = (d > 0.0f) ? rsqrtf(d) : 0.0f;
        g_dinv[t] = r;
        g_self[t] = r * r;
    }
}

// fill CSR, fusing edge coefficient computation
__global__ void k_fill(const float* __restrict__ ew) {
    int t = blockIdx.x * blockDim.x + threadIdx.x;
    if (t >= N_EDGES) return;
    int s = g_src[t], d = g_dst[t];
    int pos = atomicAdd(&g_cursor[d], 1);
    g_csr_src[pos]  = s;
    g_csr_coef[pos] = g_dinv[s] * g_dinv[d] * ew[t];
}

// ---------------- GEMM: C[M,128] = (relu? max(A,0):A) @ W[128,128] ---------
__global__ void __launch_bounds__(256) k_gemm(const float* __restrict__ A,
                                              const float* __restrict__ W,
                                              float* __restrict__ C,
                                              int M, int relu) {
    __shared__ float As[32][68];
    __shared__ float Ws[32][128];
    const int tid = threadIdx.x;
    const int tx = tid & 15, ty = tid >> 4;
    const int m0 = blockIdx.x * 64;

    float acc[4][8];
#pragma unroll
    for (int i = 0; i < 4; i++)
#pragma unroll
        for (int j = 0; j < 8; j++) acc[i][j] = 0.0f;

    for (int k0 = 0; k0 < 128; k0 += 32) {
#pragma unroll
        for (int i = 0; i < 2; i++) {
            int idx = tid + i * 256;
            int r = idx & 63;
            int c4 = idx >> 6;
            int gm = m0 + r;
            float4 v = make_float4(0.f, 0.f, 0.f, 0.f);
            if (gm < M) v = *(const float4*)&A[(size_t)gm * 128 + k0 + c4 * 4];
            if (relu) {
                v.x = fmaxf(v.x, 0.f); v.y = fmaxf(v.y, 0.f);
                v.z = fmaxf(v.z, 0.f); v.w = fmaxf(v.w, 0.f);
            }
            As[c4 * 4 + 0][r] = v.x;
            As[c4 * 4 + 1][r] = v.y;
            As[c4 * 4 + 2][r] = v.z;
            As[c4 * 4 + 3][r] = v.w;
        }
#pragma unroll
        for (int i = 0; i < 4; i++) {
            int idx = tid + i * 256;
            int r = idx >> 5;
            int c4 = idx & 31;
            *(float4*)&Ws[r][c4 * 4] =
                *(const float4*)&W[(size_t)(k0 + r) * 128 + c4 * 4];
        }
        __syncthreads();
#pragma unroll
        for (int k = 0; k < 32; k++) {
            float4 a  = *(float4*)&As[k][ty * 4];
            float4 b0 = *(float4*)&Ws[k][tx * 4];
            float4 b1 = *(float4*)&Ws[k][64 + tx * 4];
            float av[4] = {a.x, a.y, a.z, a.w};
            float bv[8] = {b0.x, b0.y, b0.z, b0.w, b1.x, b1.y, b1.z, b1.w};
#pragma unroll
            for (int i = 0; i < 4; i++)
#pragma unroll
                for (int j = 0; j < 8; j++) acc[i][j] += av[i] * bv[j];
        }
        __syncthreads();
    }
#pragma unroll
    for (int i = 0; i < 4; i++) {
        int gm = m0 + ty * 4 + i;
        if (gm < M) {
            float4 o0 = make_float4(acc[i][0], acc[i][1], acc[i][2], acc[i][3]);
            float4 o1 = make_float4(acc[i][4], acc[i][5], acc[i][6], acc[i][7]);
            *(float4*)&C[(size_t)gm * 128 + tx * 4] = o0;
            *(float4*)&C[(size_t)gm * 128 + 64 + tx * 4] = o1;
        }
    }
}

// ---------------- aggregate: out[n] = b + self[n]*hw[n] + sum coef*hw[src] --
// One warp per dst node; lane owns 4 channels (float4). 4-way unrolled edge
// loop for MLP; single store per node (no atomics).
__global__ void __launch_bounds__(256) k_aggregate(const float* __restrict__ hw,
                                                   const float* __restrict__ bias,
                                                   float* __restrict__ out) {
    int warp = (blockIdx.x * 256 + threadIdx.x) >> 5;
    int lane = threadIdx.x & 31;
    if (warp >= N_NODES) return;
    int r0 = __ldg(&g_rowptr[warp]);
    int r1 = __ldg(&g_rowptr[warp + 1]);

    float4 b = *(const float4*)&bias[lane * 4];
    float  s = g_self[warp];
    float4 v = *(const float4*)&hw[(size_t)warp * 128 + lane * 4];
    float4 a0 = make_float4(b.x + s * v.x, b.y + s * v.y,
                            b.z + s * v.z, b.w + s * v.w);
    float4 a1 = make_float4(0.f, 0.f, 0.f, 0.f);
    float4 a2 = a1, a3 = a1;

    int e = r0;
    for (; e + 4 <= r1; e += 4) {
        int   i0 = __ldg(&g_csr_src[e + 0]);
        int   i1 = __ldg(&g_csr_src[e + 1]);
        int   i2 = __ldg(&g_csr_src[e + 2]);
        int   i3 = __ldg(&g_csr_src[e + 3]);
        float c0 = __ldg(&g_csr_coef[e + 0]);
        float c1 = __ldg(&g_csr_coef[e + 1]);
        float c2 = __ldg(&g_csr_coef[e + 2]);
        float c3 = __ldg(&g_csr_coef[e + 3]);
        float4 v0 = *(const float4*)&hw[(size_t)i0 * 128 + lane * 4];
        float4 v1 = *(const float4*)&hw[(size_t)i1 * 128 + lane * 4];
        float4 v2 = *(const float4*)&hw[(size_t)i2 * 128 + lane * 4];
        float4 v3 = *(const float4*)&hw[(size_t)i3 * 128 + lane * 4];
        a0.x += c0 * v0.x; a0.y += c0 * v0.y; a0.z += c0 * v0.z; a0.w += c0 * v0.w;
        a1.x += c1 * v1.x; a1.y += c1 * v1.y; a1.z += c1 * v1.z; a1.w += c1 * v1.w;
        a2.x += c2 * v2.x; a2.y += c2 * v2.y; a2.z += c2 * v2.z; a2.w += c2 * v2.w;
        a3.x += c3 * v3.x; a3.y += c3 * v3.y; a3.z += c3 * v3.z; a3.w += c3 * v3.w;
    }
    for (; e < r1; e++) {
        int   i0 = __ldg(&g_csr_src[e]);
        float c0 = __ldg(&g_csr_coef[e]);
        float4 v0 = *(const float4*)&hw[(size_t)i0 * 128 + lane * 4];
        a0.x += c0 * v0.x; a0.y += c0 * v0.y; a0.z += c0 * v0.z; a0.w += c0 * v0.w;
    }
    float4 o = make_float4(a0.x + a1.x + a2.x + a3.x,
                           a0.y + a1.y + a2.y + a3.y,
                           a0.z + a1.z + a2.z + a3.z,
                           a0.w + a1.w + a2.w + a3.w);
    *(float4*)&out[(size_t)warp * 128 + lane * 4] = o;
}

// ---------------- mean pool ------------------------------------------------
__global__ void k_pool(const float* __restrict__ h) {
    int gt = blockIdx.x * blockDim.x + threadIdx.x;
    int lane = threadIdx.x & 31;
    int node = gt >> 5;
    if (node >= N_NODES) return;
    int g = g_batch[node];
    float4 v = *(const float4*)&h[(size_t)node * 128 + lane * 4];
    float* p = &g_emb[g * 128 + lane * 4];
    asm volatile("red.global.add.v4.f32 [%0], {%1, %2, %3, %4};"
                 :: "l"(p), "f"(v.x), "f"(v.y), "f"(v.z), "f"(v.w)
                 : "memory");
    if (lane == 0) atomicAdd(&g_gcnt[g], 1.0f);
}

// ---------------- classifier ------------------------------------------------
__global__ void k_classify(const float* __restrict__ lw1,
                           const float* __restrict__ lb1,
                           const float* __restrict__ lw2,
                           const float* __restrict__ lb2,
                           float* __restrict__ out) {
    int lane = threadIdx.x & 31;
    int g = (blockIdx.x * blockDim.x + threadIdx.x) >> 5;
    if (g >= N_GRAPHS) return;
    float inv = 1.0f / fmaxf(g_gcnt[g], 1.0f);
    float e[4];
#pragma unroll
    for (int j = 0; j < 4; j++) e[j] = g_emb[g * 128 + lane + 32 * j] * inv;
    float t[4] = {lb1[lane], lb1[lane + 32], lb1[lane + 64], lb1[lane + 96]};
#pragma unroll
    for (int k0 = 0; k0 < 4; k0++) {
#pragma unroll
        for (int kk = 0; kk < 32; kk++) {
            float a = __shfl_sync(0xffffffffu, e[k0], kk);
            int k = k0 * 32 + kk;
            t[0] += a * lw1[k * 128 + lane];
            t[1] += a * lw1[k * 128 + lane + 32];
            t[2] += a * lw1[k * 128 + lane + 64];
            t[3] += a * lw1[k * 128 + lane + 96];
        }
    }
#pragma unroll
    for (int o = 0; o < 10; o++) {
        float p = t[0] * lw2[lane * 10 + o] + t[1] * lw2[(lane + 32) * 10 + o] +
                  t[2] * lw2[(lane + 64) * 10 + o] + t[3] * lw2[(lane + 96) * 10 + o];
#pragma unroll
        for (int off = 16; off; off >>= 1)
            p += __shfl_down_sync(0xffffffffu, p, off);
        if (lane == 0) out[g * 10 + o] = p + lb2[o];
    }
}

// ---------------- launch ----------------------------------------------------
extern "C" void kernel_launch(void* const* d_in, const int* in_sizes, int n_in,
                              void* d_out, int out_size) {
    const float* x   = (const float*)d_in[0];
    const void*  ei  = d_in[1];
    const float* ew  = (const float*)d_in[2];
    const void*  bt  = d_in[3];
    const float* W1  = (const float*)d_in[4];
    const float* b1  = (const float*)d_in[5];
    const float* W2  = (const float*)d_in[6];
    const float* b2  = (const float*)d_in[7];
    const float* W3  = (const float*)d_in[8];
    const float* b3  = (const float*)d_in[9];
    const float* lw1 = (const float*)d_in[10];
    const float* lb1 = (const float*)d_in[11];
    const float* lw2 = (const float*)d_in[12];
    const float* lb2 = (const float*)d_in[13];
    float* out = (float*)d_out;

    float *bufA, *bufB, *bufC;
    cudaGetSymbolAddress((void**)&bufA, g_bufA);
    cudaGetSymbolAddress((void**)&bufB, g_bufB);
    cudaGetSymbolAddress((void**)&bufC, g_bufC);

    const int EB = (N_EDGES + 255) / 256;         // 6250
    const int NB = (N_NODES + 255) / 256;         // 196
    const int AB = (N_NODES * 32 + 255) / 256;    // 6250 (warp per node)
    const int GB = (N_NODES + 63) / 64;           // 782

    // ---- CSR + normalization build (graph-invariant, rebuilt per call) ----
    k_detect<<<1, 32>>>((const unsigned*)ei);
    k_init_nodes<<<NB, 256>>>();
    k_convert_hist<<<EB, 256>>>(ei, bt, ew);
    k_scan<<<1, 1024>>>();
    k_dinv<<<NB, 256>>>();
    k_fill<<<EB, 256>>>(ew);

    // ---- layer 1: x -> bufB ----
    k_gemm<<<GB, 256>>>(x, W1, bufA, N_NODES, 0);
    k_aggregate<<<AB, 256>>>(bufA, b1, bufB);
    // ---- layer 2: relu(bufB) -> bufC ----
    k_gemm<<<GB, 256>>>(bufB, W2, bufA, N_NODES, 1);
    k_aggregate<<<AB, 256>>>(bufA, b2, bufC);
    // ---- layer 3: relu(bufC) -> bufB ----
    k_gemm<<<GB, 256>>>(bufC, W3, bufA, N_NODES, 1);
    k_aggregate<<<AB, 256>>>(bufA, b3, bufB);

    // ---- pool + classify ----
    k_pool<<<AB, 256>>>(bufB);
    k_classify<<<(N_GRAPHS * 32 + 255) / 256, 256>>>(lw1, lb1, lw2, lb2, out);
}

// round 3
// speedup vs baseline: 1.6673x; 1.2262x over previous
#include <cuda_runtime.h>
#include <cuda_fp16.h>

#define N_NODES 50000
#define N_EDGES 1600000
#define N_GRAPHS 256
#define HID 128
#define NB 196   // ceil(N_NODES/256)

// ---------------- scratch (static device globals; no runtime alloc) --------
__device__ float   g_bufA[(size_t)N_NODES * HID];
__device__ float   g_bufB[(size_t)N_NODES * HID];
__device__ __half2 g_bufH[(size_t)N_NODES * HID / 2];  // fp16 h@W matrix
__device__ int   g_src[N_EDGES];
__device__ int   g_dst[N_EDGES];
__device__ int   g_csr_src[N_EDGES];
__device__ float g_csr_coef[N_EDGES];
__device__ int   g_cnt[N_NODES];
__device__ int   g_rowptr[N_NODES + 1];
__device__ int   g_cursor[N_NODES];
__device__ int   g_batch[N_NODES];
__device__ float g_deg[N_NODES];
__device__ float g_dinv[N_NODES];
__device__ float g_self[N_NODES];
__device__ float g_emb[N_GRAPHS * HID];
__device__ float g_gcnt[N_GRAPHS];
__device__ int   g_bsum[256];
__device__ int   g_is64;

// ---------------- dtype detection: int64 vs int32 indices ------------------
__global__ void k_detect(const unsigned* ei) {
    if (threadIdx.x == 0 && blockIdx.x == 0) {
        int is64 = 1;
#pragma unroll
        for (int i = 1; i < 16; i += 2)
            if (ei[i] != 0u) is64 = 0;
        g_is64 = is64;
    }
}

__global__ void k_init_nodes() {
    int t = blockIdx.x * blockDim.x + threadIdx.x;
    if (t < N_NODES) { g_deg[t] = 1.0f; g_cnt[t] = 0; }
    if (t < N_GRAPHS * HID) g_emb[t] = 0.0f;
    if (t < N_GRAPHS) g_gcnt[t] = 0.0f;
}

// convert indices to int32 + weighted-degree & count histogram in one pass
__global__ void k_convert_hist(const void* ei, const void* batch,
                               const float* __restrict__ ew) {
    int t = blockIdx.x * blockDim.x + threadIdx.x;
    int is64 = g_is64;
    if (t < N_EDGES) {
        int s, d;
        if (is64) {
            const long long* p = (const long long*)ei;
            s = (int)p[t]; d = (int)p[N_EDGES + t];
        } else {
            const int* p = (const int*)ei;
            s = p[t]; d = p[N_EDGES + t];
        }
        g_src[t] = s;
        g_dst[t] = d;
        atomicAdd(&g_deg[d], ew[t]);
        atomicAdd(&g_cnt[d], 1);
    }
    if (t < N_NODES) {
        g_batch[t] = is64 ? (int)((const long long*)batch)[t]
                          : ((const int*)batch)[t];
    }
}

// ---- parallel 3-stage scan -------------------------------------------------
// stage 1: per-block count sums (+ fused dinv/self, deg is final here)
__global__ void __launch_bounds__(256) k_scan1() {
    __shared__ int ws[8];
    int tid = threadIdx.x;
    int t = blockIdx.x * 256 + tid;
    int c = (t < N_NODES) ? g_cnt[t] : 0;
    int v = c;
#pragma unroll
    for (int off = 16; off; off >>= 1)
        v += __shfl_down_sync(0xffffffffu, v, off);
    if ((tid & 31) == 0) ws[tid >> 5] = v;
    __syncthreads();
    if (tid == 0) {
        int s = 0;
#pragma unroll
        for (int i = 0; i < 8; i++) s += ws[i];
        g_bsum[blockIdx.x] = s;
    }
    if (t < N_NODES) {
        float d = g_deg[t];
        float r = (d > 0.0f) ? rsqrtf(d) : 0.0f;
        g_dinv[t] = r;
        g_self[t] = r * r;
    }
}

// stage 2: exclusive scan of 196 block sums (single small block)
__global__ void __launch_bounds__(256) k_scan2() {
    __shared__ int sh[256];
    int tid = threadIdx.x;
    int v = (tid < NB) ? g_bsum[tid] : 0;
    sh[tid] = v;
    __syncthreads();
#pragma unroll
    for (int off = 1; off < 256; off <<= 1) {
        int u = (tid >= off) ? sh[tid - off] : 0;
        __syncthreads();
        sh[tid] += u;
        __syncthreads();
    }
    g_bsum[tid] = sh[tid] - v;  // exclusive
}

// stage 3: per-block inclusive scan + global base -> rowptr / cursor
__global__ void __launch_bounds__(256) k_scan3() {
    __shared__ int sh[256];
    int tid = threadIdx.x;
    int t = blockIdx.x * 256 + tid;
    int c = (t < N_NODES) ? g_cnt[t] : 0;
    sh[tid] = c;
    __syncthreads();
#pragma unroll
    for (int off = 1; off < 256; off <<= 1) {
        int u = (tid >= off) ? sh[tid - off] : 0;
        __syncthreads();
        sh[tid] += u;
        __syncthreads();
    }
    int base = g_bsum[blockIdx.x];
    if (t < N_NODES) {
        int excl = base + sh[tid] - c;
        g_rowptr[t] = excl;
        g_cursor[t] = excl;
        if (t == N_NODES - 1) g_rowptr[N_NODES] = base + sh[tid];
    }
}

// fill CSR, fusing edge coefficient computation
__global__ void k_fill(const float* __restrict__ ew) {
    int t = blockIdx.x * blockDim.x + threadIdx.x;
    if (t >= N_EDGES) return;
    int s = g_src[t], d = g_dst[t];
    int pos = atomicAdd(&g_cursor[d], 1);
    g_csr_src[pos]  = s;
    g_csr_coef[pos] = g_dinv[s] * g_dinv[d] * ew[t];
}

// ---------------- GEMM: H[M,128](fp16) = (relu? max(A,0):A) @ W[128,128] ---
__device__ __forceinline__ unsigned packh(float a, float b) {
    __half2 h = __floats2half2_rn(a, b);
    return *(unsigned*)&h;
}

__global__ void __launch_bounds__(256) k_gemm(const float* __restrict__ A,
                                              const float* __restrict__ W,
                                              __half2* __restrict__ C,
                                              int M, int relu) {
    __shared__ float As[32][68];
    __shared__ float Ws[32][128];
    const int tid = threadIdx.x;
    const int tx = tid & 15, ty = tid >> 4;
    const int m0 = blockIdx.x * 64;

    float acc[4][8];
#pragma unroll
    for (int i = 0; i < 4; i++)
#pragma unroll
        for (int j = 0; j < 8; j++) acc[i][j] = 0.0f;

    for (int k0 = 0; k0 < 128; k0 += 32) {
#pragma unroll
        for (int i = 0; i < 2; i++) {
            int idx = tid + i * 256;
            int r = idx & 63;
            int c4 = idx >> 6;
            int gm = m0 + r;
            float4 v = make_float4(0.f, 0.f, 0.f, 0.f);
            if (gm < M) v = *(const float4*)&A[(size_t)gm * 128 + k0 + c4 * 4];
            if (relu) {
                v.x = fmaxf(v.x, 0.f); v.y = fmaxf(v.y, 0.f);
                v.z = fmaxf(v.z, 0.f); v.w = fmaxf(v.w, 0.f);
            }
            As[c4 * 4 + 0][r] = v.x;
            As[c4 * 4 + 1][r] = v.y;
            As[c4 * 4 + 2][r] = v.z;
            As[c4 * 4 + 3][r] = v.w;
        }
#pragma unroll
        for (int i = 0; i < 4; i++) {
            int idx = tid + i * 256;
            int r = idx >> 5;
            int c4 = idx & 31;
            *(float4*)&Ws[r][c4 * 4] =
                *(const float4*)&W[(size_t)(k0 + r) * 128 + c4 * 4];
        }
        __syncthreads();
#pragma unroll
        for (int k = 0; k < 32; k++) {
            float4 a  = *(float4*)&As[k][ty * 4];
            float4 b0 = *(float4*)&Ws[k][tx * 4];
            float4 b1 = *(float4*)&Ws[k][64 + tx * 4];
            float av[4] = {a.x, a.y, a.z, a.w};
            float bv[8] = {b0.x, b0.y, b0.z, b0.w, b1.x, b1.y, b1.z, b1.w};
#pragma unroll
            for (int i = 0; i < 4; i++)
#pragma unroll
                for (int j = 0; j < 8; j++) acc[i][j] += av[i] * bv[j];
        }
        __syncthreads();
    }
#pragma unroll
    for (int i = 0; i < 4; i++) {
        int gm = m0 + ty * 4 + i;
        if (gm < M) {
            // channels [tx*4, tx*4+4) and [64+tx*4, 64+tx*4+4), half2 layout
            uint2 o0 = make_uint2(packh(acc[i][0], acc[i][1]),
                                  packh(acc[i][2], acc[i][3]));
            uint2 o1 = make_uint2(packh(acc[i][4], acc[i][5]),
                                  packh(acc[i][6], acc[i][7]));
            *(uint2*)&C[(size_t)gm * 64 + tx * 2]      = o0;
            *(uint2*)&C[(size_t)gm * 64 + 32 + tx * 2] = o1;
        }
    }
}

// ---------------- aggregate: out[n] = b + self[n]*hw[n] + sum coef*hw[src] --
// fp16 gather (256B/row), fp32 accumulate. One warp per dst node; lane owns
// 4 channels. 4-way unrolled for MLP; single fp32 store per node.
__global__ void __launch_bounds__(256) k_aggregate(const __half2* __restrict__ hw,
                                                   const float* __restrict__ bias,
                                                   float* __restrict__ out) {
    const uint2* hw4 = (const uint2*)hw;  // 8B = 4 halves = 4 channels
    int warp = (blockIdx.x * 256 + threadIdx.x) >> 5;
    int lane = threadIdx.x & 31;
    if (warp >= N_NODES) return;
    int r0 = __ldg(&g_rowptr[warp]);
    int r1 = __ldg(&g_rowptr[warp + 1]);

    float4 b = *(const float4*)&bias[lane * 4];
    float  s = g_self[warp];
    uint2 uself = __ldg(&hw4[(size_t)warp * 32 + lane]);
    float2 s0 = __half22float2(*(__half2*)&uself.x);
    float2 s1 = __half22float2(*(__half2*)&uself.y);
    float4 a0 = make_float4(b.x + s * s0.x, b.y + s * s0.y,
                            b.z + s * s1.x, b.w + s * s1.y);
    float4 a1 = make_float4(0.f, 0.f, 0.f, 0.f);
    float4 a2 = a1, a3 = a1;

    int e = r0;
    for (; e + 4 <= r1; e += 4) {
        int   i0 = __ldg(&g_csr_src[e + 0]);
        int   i1 = __ldg(&g_csr_src[e + 1]);
        int   i2 = __ldg(&g_csr_src[e + 2]);
        int   i3 = __ldg(&g_csr_src[e + 3]);
        float c0 = __ldg(&g_csr_coef[e + 0]);
        float c1 = __ldg(&g_csr_coef[e + 1]);
        float c2 = __ldg(&g_csr_coef[e + 2]);
        float c3 = __ldg(&g_csr_coef[e + 3]);
        uint2 u0 = __ldg(&hw4[(size_t)i0 * 32 + lane]);
        uint2 u1 = __ldg(&hw4[(size_t)i1 * 32 + lane]);
        uint2 u2 = __ldg(&hw4[(size_t)i2 * 32 + lane]);
        uint2 u3 = __ldg(&hw4[(size_t)i3 * 32 + lane]);
        float2 p, q;
        p = __half22float2(*(__half2*)&u0.x); q = __half22float2(*(__half2*)&u0.y);
        a0.x += c0 * p.x; a0.y += c0 * p.y; a0.z += c0 * q.x; a0.w += c0 * q.y;
        p = __half22float2(*(__half2*)&u1.x); q = __half22float2(*(__half2*)&u1.y);
        a1.x += c1 * p.x; a1.y += c1 * p.y; a1.z += c1 * q.x; a1.w += c1 * q.y;
        p = __half22float2(*(__half2*)&u2.x); q = __half22float2(*(__half2*)&u2.y);
        a2.x += c2 * p.x; a2.y += c2 * p.y; a2.z += c2 * q.x; a2.w += c2 * q.y;
        p = __half22float2(*(__half2*)&u3.x); q = __half22float2(*(__half2*)&u3.y);
        a3.x += c3 * p.x; a3.y += c3 * p.y; a3.z += c3 * q.x; a3.w += c3 * q.y;
    }
    for (; e < r1; e++) {
        int   i0 = __ldg(&g_csr_src[e]);
        float c0 = __ldg(&g_csr_coef[e]);
        uint2 u0 = __ldg(&hw4[(size_t)i0 * 32 + lane]);
        float2 p = __half22float2(*(__half2*)&u0.x);
        float2 q = __half22float2(*(__half2*)&u0.y);
        a0.x += c0 * p.x; a0.y += c0 * p.y; a0.z += c0 * q.x; a0.w += c0 * q.y;
    }
    float4 o = make_float4(a0.x + a1.x + a2.x + a3.x,
                           a0.y + a1.y + a2.y + a3.y,
                           a0.z + a1.z + a2.z + a3.z,
                           a0.w + a1.w + a2.w + a3.w);
    *(float4*)&out[(size_t)warp * 128 + lane * 4] = o;
}

// ---------------- mean pool ------------------------------------------------
__global__ void k_pool(const float* __restrict__ h) {
    int gt = blockIdx.x * blockDim.x + threadIdx.x;
    int lane = threadIdx.x & 31;
    int node = gt >> 5;
    if (node >= N_NODES) return;
    int g = g_batch[node];
    float4 v = *(const float4*)&h[(size_t)node * 128 + lane * 4];
    float* p = &g_emb[g * 128 + lane * 4];
    asm volatile("red.global.add.v4.f32 [%0], {%1, %2, %3, %4};"
                 :: "l"(p), "f"(v.x), "f"(v.y), "f"(v.z), "f"(v.w)
                 : "memory");
    if (lane == 0) atomicAdd(&g_gcnt[g], 1.0f);
}

// ---------------- classifier ------------------------------------------------
__global__ void k_classify(const float* __restrict__ lw1,
                           const float* __restrict__ lb1,
                           const float* __restrict__ lw2,
                           const float* __restrict__ lb2,
                           float* __restrict__ out) {
    int lane = threadIdx.x & 31;
    int g = (blockIdx.x * blockDim.x + threadIdx.x) >> 5;
    if (g >= N_GRAPHS) return;
    float inv = 1.0f / fmaxf(g_gcnt[g], 1.0f);
    float e[4];
#pragma unroll
    for (int j = 0; j < 4; j++) e[j] = g_emb[g * 128 + lane + 32 * j] * inv;
    float t[4] = {lb1[lane], lb1[lane + 32], lb1[lane + 64], lb1[lane + 96]};
#pragma unroll
    for (int k0 = 0; k0 < 4; k0++) {
#pragma unroll
        for (int kk = 0; kk < 32; kk++) {
            float a = __shfl_sync(0xffffffffu, e[k0], kk);
            int k = k0 * 32 + kk;
            t[0] += a * lw1[k * 128 + lane];
            t[1] += a * lw1[k * 128 + lane + 32];
            t[2] += a * lw1[k * 128 + lane + 64];
            t[3] += a * lw1[k * 128 + lane + 96];
        }
    }
#pragma unroll
    for (int o = 0; o < 10; o++) {
        float p = t[0] * lw2[lane * 10 + o] + t[1] * lw2[(lane + 32) * 10 + o] +
                  t[2] * lw2[(lane + 64) * 10 + o] + t[3] * lw2[(lane + 96) * 10 + o];
#pragma unroll
        for (int off = 16; off; off >>= 1)
            p += __shfl_down_sync(0xffffffffu, p, off);
        if (lane == 0) out[g * 10 + o] = p + lb2[o];
    }
}

// ---------------- launch ----------------------------------------------------
extern "C" void kernel_launch(void* const* d_in, const int* in_sizes, int n_in,
                              void* d_out, int out_size) {
    const float* x   = (const float*)d_in[0];
    const void*  ei  = d_in[1];
    const float* ew  = (const float*)d_in[2];
    const void*  bt  = d_in[3];
    const float* W1  = (const float*)d_in[4];
    const float* b1  = (const float*)d_in[5];
    const float* W2  = (const float*)d_in[6];
    const float* b2  = (const float*)d_in[7];
    const float* W3  = (const float*)d_in[8];
    const float* b3  = (const float*)d_in[9];
    const float* lw1 = (const float*)d_in[10];
    const float* lb1 = (const float*)d_in[11];
    const float* lw2 = (const float*)d_in[12];
    const float* lb2 = (const float*)d_in[13];
    float* out = (float*)d_out;

    float *bufA, *bufB;
    __half2* bufH;
    cudaGetSymbolAddress((void**)&bufA, g_bufA);
    cudaGetSymbolAddress((void**)&bufB, g_bufB);
    cudaGetSymbolAddress((void**)&bufH, g_bufH);

    const int EB = (N_EDGES + 255) / 256;         // 6250
    const int AB = (N_NODES * 32 + 255) / 256;    // 6250 (warp per node)
    const int GB = (N_NODES + 63) / 64;           // 782

    // ---- CSR + normalization build (graph-invariant, rebuilt per call) ----
    k_detect<<<1, 32>>>((const unsigned*)ei);
    k_init_nodes<<<NB, 256>>>();
    k_convert_hist<<<EB, 256>>>(ei, bt, ew);
    k_scan1<<<NB, 256>>>();
    k_scan2<<<1, 256>>>();
    k_scan3<<<NB, 256>>>();
    k_fill<<<EB, 256>>>(ew);

    // ---- layer 1: x -> bufA ----
    k_gemm<<<GB, 256>>>(x, W1, bufH, N_NODES, 0);
    k_aggregate<<<AB, 256>>>(bufH, b1, bufA);
    // ---- layer 2: relu(bufA) -> bufB ----
    k_gemm<<<GB, 256>>>(bufA, W2, bufH, N_NODES, 1);
    k_aggregate<<<AB, 256>>>(bufH, b2, bufB);
    // ---- layer 3: relu(bufB) -> bufA ----
    k_gemm<<<GB, 256>>>(bufB, W3, bufH, N_NODES, 1);
    k_aggregate<<<AB, 256>>>(bufH, b3, bufA);

    // ---- pool + classify ----
    k_pool<<<AB, 256>>>(bufA);
    k_classify<<<(N_GRAPHS * 32 + 255) / 256, 256>>>(lw1, lb1, lw2, lb2, out);
}

// round 4
// speedup vs baseline: 2.4364x; 1.4613x over previous
#include <cuda_runtime.h>
#include <cuda_fp16.h>

#define N_NODES 50000
#define N_EDGES 1600000
#define N_GRAPHS 256
#define HID 128
#define NB 196   // ceil(N_NODES/256)

// ---------------- scratch (static device globals; no runtime alloc) --------
__device__ float   g_bufA[(size_t)N_NODES * HID];
__device__ float   g_bufB[(size_t)N_NODES * HID];
__device__ __half2 g_bufH[(size_t)N_NODES * HID / 2];  // fp16 h@W matrix
__device__ int   g_src[N_EDGES];
__device__ int   g_dst[N_EDGES];
__device__ int   g_csr_src[N_EDGES];
__device__ float g_csr_coef[N_EDGES];
__device__ int   g_cnt[N_NODES];
__device__ int   g_rowptr[N_NODES + 1];
__device__ int   g_cursor[N_NODES];
__device__ int   g_batch[N_NODES];
__device__ float g_deg[N_NODES];
__device__ float g_dinv[N_NODES];
__device__ float g_self[N_NODES];
__device__ float g_emb[N_GRAPHS * HID];
__device__ float g_gcnt[N_GRAPHS];
__device__ int   g_bsum[256];
__device__ int   g_is64;

// ---------------- dtype detection: int64 vs int32 indices ------------------
__global__ void k_detect(const unsigned* ei) {
    if (threadIdx.x == 0 && blockIdx.x == 0) {
        int is64 = 1;
#pragma unroll
        for (int i = 1; i < 16; i += 2)
            if (ei[i] != 0u) is64 = 0;
        g_is64 = is64;
    }
}

__global__ void k_init_nodes() {
    int t = blockIdx.x * blockDim.x + threadIdx.x;
    if (t < N_NODES) { g_deg[t] = 1.0f; g_cnt[t] = 0; }
    if (t < N_GRAPHS * HID) g_emb[t] = 0.0f;
    if (t < N_GRAPHS) g_gcnt[t] = 0.0f;
}

// indices -> int32, degree/count histogram, graph-size counts, in one pass
__global__ void k_convert_hist(const void* ei, const void* batch,
                               const float* __restrict__ ew) {
    int t = blockIdx.x * blockDim.x + threadIdx.x;
    int is64 = g_is64;
    if (t < N_EDGES) {
        int s, d;
        if (is64) {
            const long long* p = (const long long*)ei;
            s = (int)p[t]; d = (int)p[N_EDGES + t];
        } else {
            const int* p = (const int*)ei;
            s = p[t]; d = p[N_EDGES + t];
        }
        g_src[t] = s;
        g_dst[t] = d;
        atomicAdd(&g_deg[d], ew[t]);
        atomicAdd(&g_cnt[d], 1);
    }
    if (t < N_NODES) {
        int b = is64 ? (int)((const long long*)batch)[t]
                     : ((const int*)batch)[t];
        g_batch[t] = b;
        atomicAdd(&g_gcnt[b], 1.0f);
    }
}

// ---- parallel 3-stage scan --------------------------------------------------
__global__ void __launch_bounds__(256) k_scan1() {
    __shared__ int ws[8];
    int tid = threadIdx.x;
    int t = blockIdx.x * 256 + tid;
    int c = (t < N_NODES) ? g_cnt[t] : 0;
    int v = c;
#pragma unroll
    for (int off = 16; off; off >>= 1)
        v += __shfl_down_sync(0xffffffffu, v, off);
    if ((tid & 31) == 0) ws[tid >> 5] = v;
    __syncthreads();
    if (tid == 0) {
        int s = 0;
#pragma unroll
        for (int i = 0; i < 8; i++) s += ws[i];
        g_bsum[blockIdx.x] = s;
    }
    if (t < N_NODES) {
        float d = g_deg[t];
        float r = (d > 0.0f) ? rsqrtf(d) : 0.0f;
        g_dinv[t] = r;
        g_self[t] = r * r;
    }
}

__global__ void __launch_bounds__(256) k_scan2() {
    __shared__ int sh[256];
    int tid = threadIdx.x;
    int v = (tid < NB) ? g_bsum[tid] : 0;
    sh[tid] = v;
    __syncthreads();
#pragma unroll
    for (int off = 1; off < 256; off <<= 1) {
        int u = (tid >= off) ? sh[tid - off] : 0;
        __syncthreads();
        sh[tid] += u;
        __syncthreads();
    }
    g_bsum[tid] = sh[tid] - v;  // exclusive
}

__global__ void __launch_bounds__(256) k_scan3() {
    __shared__ int sh[256];
    int tid = threadIdx.x;
    int t = blockIdx.x * 256 + tid;
    int c = (t < N_NODES) ? g_cnt[t] : 0;
    sh[tid] = c;
    __syncthreads();
#pragma unroll
    for (int off = 1; off < 256; off <<= 1) {
        int u = (tid >= off) ? sh[tid - off] : 0;
        __syncthreads();
        sh[tid] += u;
        __syncthreads();
    }
    int base = g_bsum[blockIdx.x];
    if (t < N_NODES) {
        int excl = base + sh[tid] - c;
        g_rowptr[t] = excl;
        g_cursor[t] = excl;
        if (t == N_NODES - 1) g_rowptr[N_NODES] = base + sh[tid];
    }
}

__global__ void k_fill(const float* __restrict__ ew) {
    int t = blockIdx.x * blockDim.x + threadIdx.x;
    if (t >= N_EDGES) return;
    int s = g_src[t], d = g_dst[t];
    int pos = atomicAdd(&g_cursor[d], 1);
    g_csr_src[pos]  = s;
    g_csr_coef[pos] = g_dinv[s] * g_dinv[d] * ew[t];
}

// ---------------- tensor-core GEMM ------------------------------------------
// H[M,128](fp16) = (relu? max(A,0):A)(fp32->fp16) @ W[128,128](fp32->fp16)
// fp32 accumulate via mma.sync.m16n8k16. BM=64, BN=128 (full), BK=128 (full).
// 256 threads / 8 warps: warp grid 2(M) x 4(N), warp tile 32x32.
__device__ __forceinline__ void ldsm_x4(unsigned& r0, unsigned& r1,
                                        unsigned& r2, unsigned& r3, unsigned a) {
    asm volatile("ldmatrix.sync.aligned.m8n8.x4.shared.b16 {%0,%1,%2,%3}, [%4];"
                 : "=r"(r0), "=r"(r1), "=r"(r2), "=r"(r3) : "r"(a));
}
__device__ __forceinline__ void ldsm_x4t(unsigned& r0, unsigned& r1,
                                         unsigned& r2, unsigned& r3, unsigned a) {
    asm volatile("ldmatrix.sync.aligned.m8n8.x4.trans.shared.b16 {%0,%1,%2,%3}, [%4];"
                 : "=r"(r0), "=r"(r1), "=r"(r2), "=r"(r3) : "r"(a));
}
__device__ __forceinline__ void mma16816(float* c, const unsigned* a,
                                         const unsigned* b) {
    asm volatile("mma.sync.aligned.m16n8k16.row.col.f32.f16.f16.f32 "
                 "{%0,%1,%2,%3}, {%4,%5,%6,%7}, {%8,%9}, {%0,%1,%2,%3};"
                 : "+f"(c[0]), "+f"(c[1]), "+f"(c[2]), "+f"(c[3])
                 : "r"(a[0]), "r"(a[1]), "r"(a[2]), "r"(a[3]),
                   "r"(b[0]), "r"(b[1]));
}

__global__ void __launch_bounds__(256) k_gemm_tc(const float* __restrict__ A,
                                                 const float* __restrict__ W,
                                                 __half2* __restrict__ C,
                                                 int M, int relu) {
    // swizzled fp16 tiles: rows of 256B; 16B unit index XORed with (row&7)
    __shared__ __align__(16) unsigned char s_a[64 * 256];   // 16 KB
    __shared__ __align__(16) unsigned char s_w[128 * 256];  // 32 KB
    const int tid = threadIdx.x;
    const int m0 = blockIdx.x * 64;

    // ---- load A (64x128 fp32 -> fp16, optional relu), coalesced ----
#pragma unroll
    for (int i = 0; i < 8; i++) {
        int f = i * 256 + tid;      // float4 id (2048)
        int r = f >> 5, c4 = f & 31;
        int gm = m0 + r;
        float4 v = make_float4(0.f, 0.f, 0.f, 0.f);
        if (gm < M) v = *(const float4*)&A[(size_t)gm * 128 + c4 * 4];
        if (relu) {
            v.x = fmaxf(v.x, 0.f); v.y = fmaxf(v.y, 0.f);
            v.z = fmaxf(v.z, 0.f); v.w = fmaxf(v.w, 0.f);
        }
        __half2 h0 = __floats2half2_rn(v.x, v.y);
        __half2 h1 = __floats2half2_rn(v.z, v.w);
        unsigned byte = (unsigned)(r * 256 + c4 * 8);
        unsigned swb = byte ^ ((unsigned)(r & 7) << 4);
        uint2 u = make_uint2(*(unsigned*)&h0, *(unsigned*)&h1);
        *(uint2*)(s_a + swb) = u;
    }
    // ---- load W (128x128 fp32 -> fp16), coalesced ----
#pragma unroll
    for (int i = 0; i < 16; i++) {
        int f = i * 256 + tid;      // float4 id (4096)
        int r = f >> 5, c4 = f & 31;
        float4 v = *(const float4*)&W[(size_t)r * 128 + c4 * 4];
        __half2 h0 = __floats2half2_rn(v.x, v.y);
        __half2 h1 = __floats2half2_rn(v.z, v.w);
        unsigned byte = (unsigned)(r * 256 + c4 * 8);
        unsigned swb = byte ^ ((unsigned)(r & 7) << 4);
        uint2 u = make_uint2(*(unsigned*)&h0, *(unsigned*)&h1);
        *(uint2*)(s_w + swb) = u;
    }
    __syncthreads();

    const int lane = tid & 31;
    const int wid = tid >> 5;
    const int wm = wid >> 2, wn = wid & 3;   // warp tile: rows wm*32, cols wn*32
    unsigned sa = (unsigned)__cvta_generic_to_shared(s_a);
    unsigned sw = (unsigned)__cvta_generic_to_shared(s_w);

    float acc[2][4][4];
#pragma unroll
    for (int mt = 0; mt < 2; mt++)
#pragma unroll
        for (int nt = 0; nt < 4; nt++)
#pragma unroll
            for (int j = 0; j < 4; j++) acc[mt][nt][j] = 0.0f;

    const int a_r0 = wm * 32 + (lane & 15);   // +16 for mt=1
    const int a_kh = (lane >> 4) * 8;         // half index within k-step
    const int b_kr = (lane & 7) + ((lane >> 3) & 1) * 8;
    const int b_n0 = wn * 32 + (lane >> 4) * 8;   // +16 for pair 1

#pragma unroll
    for (int ks = 0; ks < 8; ks++) {
        unsigned a[2][4], b[4][2];
#pragma unroll
        for (int mt = 0; mt < 2; mt++) {
            int row = a_r0 + mt * 16;
            unsigned byte = (unsigned)(row * 256 + (ks * 16 + a_kh) * 2);
            unsigned ad = sa + (byte ^ ((unsigned)(row & 7) << 4));
            ldsm_x4(a[mt][0], a[mt][1], a[mt][2], a[mt][3], ad);
        }
#pragma unroll
        for (int p = 0; p < 2; p++) {
            int k = ks * 16 + b_kr;
            unsigned byte = (unsigned)(k * 256 + (b_n0 + p * 16) * 2);
            unsigned ad = sw + (byte ^ ((unsigned)(k & 7) << 4));
            ldsm_x4t(b[2 * p][0], b[2 * p][1], b[2 * p + 1][0], b[2 * p + 1][1], ad);
        }
#pragma unroll
        for (int mt = 0; mt < 2; mt++)
#pragma unroll
            for (int nt = 0; nt < 4; nt++)
                mma16816(acc[mt][nt], a[mt], b[nt]);
    }

    // ---- epilogue: fp16 store ----
#pragma unroll
    for (int mt = 0; mt < 2; mt++) {
        int r0 = m0 + wm * 32 + mt * 16 + (lane >> 2);
#pragma unroll
        for (int nt = 0; nt < 4; nt++) {
            int ci = wn * 16 + nt * 4 + (lane & 3);   // half2 column index
            if (r0 < M)
                C[(size_t)r0 * 64 + ci] = __floats2half2_rn(acc[mt][nt][0], acc[mt][nt][1]);
            if (r0 + 8 < M)
                C[(size_t)(r0 + 8) * 64 + ci] = __floats2half2_rn(acc[mt][nt][2], acc[mt][nt][3]);
        }
    }
}

// ---------------- aggregate: out[n] = b + self[n]*hw[n] + sum coef*hw[src] --
__device__ __forceinline__ float4 agg_node(const uint2* __restrict__ hw4,
                                           const float* __restrict__ bias,
                                           int node, int lane) {
    int r0 = __ldg(&g_rowptr[node]);
    int r1 = __ldg(&g_rowptr[node + 1]);

    float4 b = *(const float4*)&bias[lane * 4];
    float  s = g_self[node];
    uint2 uself = __ldg(&hw4[(size_t)node * 32 + lane]);
    float2 s0 = __half22float2(*(__half2*)&uself.x);
    float2 s1 = __half22float2(*(__half2*)&uself.y);
    float4 a0 = make_float4(b.x + s * s0.x, b.y + s * s0.y,
                            b.z + s * s1.x, b.w + s * s1.y);
    float4 a1 = make_float4(0.f, 0.f, 0.f, 0.f);
    float4 a2 = a1, a3 = a1;

    int e = r0;
    for (; e + 4 <= r1; e += 4) {
        int   i0 = __ldg(&g_csr_src[e + 0]);
        int   i1 = __ldg(&g_csr_src[e + 1]);
        int   i2 = __ldg(&g_csr_src[e + 2]);
        int   i3 = __ldg(&g_csr_src[e + 3]);
        float c0 = __ldg(&g_csr_coef[e + 0]);
        float c1 = __ldg(&g_csr_coef[e + 1]);
        float c2 = __ldg(&g_csr_coef[e + 2]);
        float c3 = __ldg(&g_csr_coef[e + 3]);
        uint2 u0 = __ldg(&hw4[(size_t)i0 * 32 + lane]);
        uint2 u1 = __ldg(&hw4[(size_t)i1 * 32 + lane]);
        uint2 u2 = __ldg(&hw4[(size_t)i2 * 32 + lane]);
        uint2 u3 = __ldg(&hw4[(size_t)i3 * 32 + lane]);
        float2 p, q;
        p = __half22float2(*(__half2*)&u0.x); q = __half22float2(*(__half2*)&u0.y);
        a0.x += c0 * p.x; a0.y += c0 * p.y; a0.z += c0 * q.x; a0.w += c0 * q.y;
        p = __half22float2(*(__half2*)&u1.x); q = __half22float2(*(__half2*)&u1.y);
        a1.x += c1 * p.x; a1.y += c1 * p.y; a1.z += c1 * q.x; a1.w += c1 * q.y;
        p = __half22float2(*(__half2*)&u2.x); q = __half22float2(*(__half2*)&u2.y);
        a2.x += c2 * p.x; a2.y += c2 * p.y; a2.z += c2 * q.x; a2.w += c2 * q.y;
        p = __half22float2(*(__half2*)&u3.x); q = __half22float2(*(__half2*)&u3.y);
        a3.x += c3 * p.x; a3.y += c3 * p.y; a3.z += c3 * q.x; a3.w += c3 * q.y;
    }
    for (; e < r1; e++) {
        int   i0 = __ldg(&g_csr_src[e]);
        float c0 = __ldg(&g_csr_coef[e]);
        uint2 u0 = __ldg(&hw4[(size_t)i0 * 32 + lane]);
        float2 p = __half22float2(*(__half2*)&u0.x);
        float2 q = __half22float2(*(__half2*)&u0.y);
        a0.x += c0 * p.x; a0.y += c0 * p.y; a0.z += c0 * q.x; a0.w += c0 * q.y;
    }
    return make_float4(a0.x + a1.x + a2.x + a3.x,
                       a0.y + a1.y + a2.y + a3.y,
                       a0.z + a1.z + a2.z + a3.z,
                       a0.w + a1.w + a2.w + a3.w);
}

__global__ void __launch_bounds__(256) k_aggregate(const __half2* __restrict__ hw,
                                                   const float* __restrict__ bias,
                                                   float* __restrict__ out) {
    int node = (blockIdx.x * 256 + threadIdx.x) >> 5;
    int lane = threadIdx.x & 31;
    if (node >= N_NODES) return;
    float4 o = agg_node((const uint2*)hw, bias, node, lane);
    *(float4*)&out[(size_t)node * 128 + lane * 4] = o;
}

// layer-3 aggregate fused with mean-pool accumulation (no node output)
__global__ void __launch_bounds__(256) k_aggregate_pool(const __half2* __restrict__ hw,
                                                        const float* __restrict__ bias) {
    int node = (blockIdx.x * 256 + threadIdx.x) >> 5;
    int lane = threadIdx.x & 31;
    if (node >= N_NODES) return;
    float4 o = agg_node((const uint2*)hw, bias, node, lane);
    int g = g_batch[node];
    float* p = &g_emb[g * 128 + lane * 4];
    asm volatile("red.global.add.v4.f32 [%0], {%1, %2, %3, %4};"
                 :: "l"(p), "f"(o.x), "f"(o.y), "f"(o.z), "f"(o.w)
                 : "memory");
}

// ---------------- classifier ------------------------------------------------
__global__ void k_classify(const float* __restrict__ lw1,
                           const float* __restrict__ lb1,
                           const float* __restrict__ lw2,
                           const float* __restrict__ lb2,
                           float* __restrict__ out) {
    int lane = threadIdx.x & 31;
    int g = (blockIdx.x * blockDim.x + threadIdx.x) >> 5;
    if (g >= N_GRAPHS) return;
    float inv = 1.0f / fmaxf(g_gcnt[g], 1.0f);
    float e[4];
#pragma unroll
    for (int j = 0; j < 4; j++) e[j] = g_emb[g * 128 + lane + 32 * j] * inv;
    float t[4] = {lb1[lane], lb1[lane + 32], lb1[lane + 64], lb1[lane + 96]};
#pragma unroll
    for (int k0 = 0; k0 < 4; k0++) {
#pragma unroll
        for (int kk = 0; kk < 32; kk++) {
            float a = __shfl_sync(0xffffffffu, e[k0], kk);
            int k = k0 * 32 + kk;
            t[0] += a * lw1[k * 128 + lane];
            t[1] += a * lw1[k * 128 + lane + 32];
            t[2] += a * lw1[k * 128 + lane + 64];
            t[3] += a * lw1[k * 128 + lane + 96];
        }
    }
#pragma unroll
    for (int o = 0; o < 10; o++) {
        float p = t[0] * lw2[lane * 10 + o] + t[1] * lw2[(lane + 32) * 10 + o] +
                  t[2] * lw2[(lane + 64) * 10 + o] + t[3] * lw2[(lane + 96) * 10 + o];
#pragma unroll
        for (int off = 16; off; off >>= 1)
            p += __shfl_down_sync(0xffffffffu, p, off);
        if (lane == 0) out[g * 10 + o] = p + lb2[o];
    }
}

// ---------------- launch ----------------------------------------------------
extern "C" void kernel_launch(void* const* d_in, const int* in_sizes, int n_in,
                              void* d_out, int out_size) {
    const float* x   = (const float*)d_in[0];
    const void*  ei  = d_in[1];
    const float* ew  = (const float*)d_in[2];
    const void*  bt  = d_in[3];
    const float* W1  = (const float*)d_in[4];
    const float* b1  = (const float*)d_in[5];
    const float* W2  = (const float*)d_in[6];
    const float* b2  = (const float*)d_in[7];
    const float* W3  = (const float*)d_in[8];
    const float* b3  = (const float*)d_in[9];
    const float* lw1 = (const float*)d_in[10];
    const float* lb1 = (const float*)d_in[11];
    const float* lw2 = (const float*)d_in[12];
    const float* lb2 = (const float*)d_in[13];
    float* out = (float*)d_out;

    float *bufA, *bufB;
    __half2* bufH;
    cudaGetSymbolAddress((void**)&bufA, g_bufA);
    cudaGetSymbolAddress((void**)&bufB, g_bufB);
    cudaGetSymbolAddress((void**)&bufH, g_bufH);

    const int EB = (N_EDGES + 255) / 256;         // 6250
    const int AB = (N_NODES * 32 + 255) / 256;    // 6250 (warp per node)
    const int GB = (N_NODES + 63) / 64;           // 782

    // ---- CSR + normalization build ----
    k_detect<<<1, 32>>>((const unsigned*)ei);
    k_init_nodes<<<NB, 256>>>();
    k_convert_hist<<<EB, 256>>>(ei, bt, ew);
    k_scan1<<<NB, 256>>>();
    k_scan2<<<1, 256>>>();
    k_scan3<<<NB, 256>>>();
    k_fill<<<EB, 256>>>(ew);

    // ---- layer 1: x -> bufA ----
    k_gemm_tc<<<GB, 256>>>(x, W1, bufH, N_NODES, 0);
    k_aggregate<<<AB, 256>>>(bufH, b1, bufA);
    // ---- layer 2: relu(bufA) -> bufB ----
    k_gemm_tc<<<GB, 256>>>(bufA, W2, bufH, N_NODES, 1);
    k_aggregate<<<AB, 256>>>(bufH, b2, bufB);
    // ---- layer 3: relu(bufB) -> pooled emb (fused) ----
    k_gemm_tc<<<GB, 256>>>(bufB, W3, bufH, N_NODES, 1);
    k_aggregate_pool<<<AB, 256>>>(bufH, b3);

    // ---- classify ----
    k_classify<<<(N_GRAPHS * 32 + 255) / 256, 256>>>(lw1, lb1, lw2, lb2, out);
}